// round 14
// baseline (speedup 1.0000x reference)
#include <cuda_runtime.h>
#include <cuda_fp16.h>
#include <cstdint>

#define D 128
#define NNODES 50000
#define NEDGES 600000
#define THREADS 256
#define SCAN_BLOCKS ((NNODES + 255) / 256)   // 196

// ---------------------------------------------------------------------------
// Device-global scratch (allocation-free rule)
// ---------------------------------------------------------------------------
__device__ __half g_inh[(size_t)NNODES * D];  // fp16 copy of inputs
__device__ __half g_xh[(size_t)NNODES * D];   // gathered features (fp16)
__device__ __half g_hh[(size_t)NNODES * D];   // layer-1 output (fp16)
__device__ int   g_deg[NNODES];
__device__ int   g_off[NNODES + 1];
__device__ int   g_seq[NEDGES];               // per-edge within-node sequence #
__device__ int   g_adj[NEDGES];
__device__ int   g_bsum[256];                 // block aggregates -> excl prefixes
__device__ int   g_done;                      // arrival counter (reset each call)
__device__ volatile int g_ready;              // prefix-ready flag (reset each call)
// fp16 weights, K-major [n][k], 4 matrices: W1a, W1b, W2a, W2b
__device__ __half g_w[4 * D * D];

// ---------------------------------------------------------------------------
// helpers
// ---------------------------------------------------------------------------
__device__ __forceinline__ uint32_t smem_u32(const void* p) {
    uint32_t a;
    asm("{ .reg .u64 t; cvta.to.shared.u64 t, %1; cvt.u32.u64 %0, t; }" : "=r"(a) : "l"(p));
    return a;
}

__device__ __forceinline__ void ldsm_x4(uint32_t& r0, uint32_t& r1, uint32_t& r2, uint32_t& r3,
                                        uint32_t addr) {
    asm volatile("ldmatrix.sync.aligned.m8n8.x4.shared.b16 {%0,%1,%2,%3}, [%4];"
                 : "=r"(r0), "=r"(r1), "=r"(r2), "=r"(r3) : "r"(addr));
}

__device__ __forceinline__ void mma_f16(float& c0, float& c1, float& c2, float& c3,
                                        uint32_t a0, uint32_t a1, uint32_t a2, uint32_t a3,
                                        uint32_t b0, uint32_t b1) {
    asm volatile("mma.sync.aligned.m16n8k16.row.col.f32.f16.f16.f32 "
                 "{%0,%1,%2,%3}, {%4,%5,%6,%7}, {%8,%9}, {%0,%1,%2,%3};"
                 : "+f"(c0), "+f"(c1), "+f"(c2), "+f"(c3)
                 : "r"(a0), "r"(a1), "r"(a2), "r"(a3), "r"(b0), "r"(b1));
}

__device__ __forceinline__ uint32_t pack2h(float v0, float v1) {
    __half2 h = __floats2half2_rn(v0, v1);
    return *(uint32_t*)&h;
}

__device__ __forceinline__ float2 h2f(uint32_t u) {
    __half2 h = *(__half2*)&u;
    return __half22float2(h);
}

// ---------------------------------------------------------------------------
// 0: histogram (stores per-edge seq) + fp32->fp16 conversion + epoch reset
// ---------------------------------------------------------------------------
__global__ void k_hist_cvt(const int* __restrict__ dst, const float* __restrict__ inputs) {
    int gid = blockIdx.x * blockDim.x + threadIdx.x;
    if (gid == 0) { g_done = 0; g_ready = 0; }   // reset scan epoch for this call
    if (gid < NEDGES / 2) {
        int2 d2 = ((const int2*)dst)[gid];
        int s0 = atomicAdd(&g_deg[d2.x], 1);
        int s1 = atomicAdd(&g_deg[d2.y], 1);
        ((int2*)g_seq)[gid] = make_int2(s0, s1);
    }
    const int total = NNODES * D / 8;
    const int stride = gridDim.x * blockDim.x;
    for (int i = gid; i < total; i += stride) {
        float4 a = ((const float4*)inputs)[i * 2];
        float4 b = ((const float4*)inputs)[i * 2 + 1];
        uint4 o;
        o.x = pack2h(a.x, a.y);
        o.y = pack2h(a.z, a.w);
        o.z = pack2h(b.x, b.y);
        o.w = pack2h(b.z, b.w);
        ((uint4*)g_inh)[i] = o;
    }
}

// ---------------------------------------------------------------------------
// 1: SINGLE-PASS scan (last-block pattern) + fused weight convert
//    grid = 256 blocks; blocks 0..195 scan, all blocks do wsplit.
// ---------------------------------------------------------------------------
__global__ __launch_bounds__(256)
void k_scan_wsplit(const float* __restrict__ W0, const float* __restrict__ W1,
                   const float* __restrict__ W2, const float* __restrict__ W3) {
    __shared__ int wsum[8];
    __shared__ int sh_last;
    const int b = blockIdx.x, tid = threadIdx.x, lane = tid & 31, wd = tid >> 5;

    if (b < SCAN_BLOCKS) {
        int i = b * 256 + tid;
        int v = (i < NNODES) ? g_deg[i] : 0;
        if (i < NNODES) g_deg[i] = 0;            // re-zero for next call
        int s = v;
        #pragma unroll
        for (int o = 1; o < 32; o <<= 1) {
            int t = __shfl_up_sync(0xFFFFFFFFu, s, o);
            if (lane >= o) s += t;
        }
        if (lane == 31) wsum[wd] = s;
        __syncthreads();
        if (wd == 0) {
            int x = (lane < 8) ? wsum[lane] : 0;
            #pragma unroll
            for (int o = 1; o < 8; o <<= 1) {
                int t = __shfl_up_sync(0xFFFFFFFFu, x, o);
                if (lane >= o) x += t;
            }
            if (lane < 8) wsum[lane] = x;
        }
        __syncthreads();
        int excl_local = (wd ? wsum[wd - 1] : 0) + s - v;   // chunk-local excl prefix

        // publish aggregate, detect last-arriving block
        if (tid == 255) {
            g_bsum[b] = wsum[7];
            __threadfence();
            int d = atomicAdd(&g_done, 1);
            sh_last = (d == SCAN_BLOCKS - 1) ? 1 : 0;
        }
        __syncthreads();

        if (sh_last) {
            // this block scans the 196 aggregates -> exclusive prefixes
            __threadfence();                      // ensure all aggs visible
            int v2 = (tid < SCAN_BLOCKS) ? g_bsum[tid] : 0;
            int s2 = v2;
            #pragma unroll
            for (int o = 1; o < 32; o <<= 1) {
                int t = __shfl_up_sync(0xFFFFFFFFu, s2, o);
                if (lane >= o) s2 += t;
            }
            if (lane == 31) wsum[wd] = s2;
            __syncthreads();
            if (wd == 0) {
                int x = (lane < 8) ? wsum[lane] : 0;
                #pragma unroll
                for (int o = 1; o < 8; o <<= 1) {
                    int t = __shfl_up_sync(0xFFFFFFFFu, x, o);
                    if (lane >= o) x += t;
                }
                if (lane < 8) wsum[lane] = x;
            }
            __syncthreads();
            int excl2 = (wd ? wsum[wd - 1] : 0) + s2 - v2;
            if (tid < SCAN_BLOCKS) g_bsum[tid] = excl2;
            __threadfence();
            __syncthreads();
            if (tid == 0) g_ready = 1;
        }

        // all scan blocks wait for prefixes (all 256 blocks co-resident -> safe)
        if (tid == 0) {
            while (g_ready == 0) { __nanosleep(40); }
        }
        __syncthreads();
        __threadfence();                          // acquire g_bsum prefixes

        int pre = g_bsum[b];
        if (i < NNODES) g_off[i] = excl_local + pre;
        if (b == 0 && tid == 0) g_off[NNODES] = NEDGES;
    }

    // fused weight transpose + fp16 convert: 4*128*128 = 65536 = grid exactly
    {
        int gidx = b * 256 + tid;
        int mat = gidx >> 14;
        int idx = gidx & 16383;
        const float* W = (mat == 0) ? W0 : (mat == 1) ? W1 : (mat == 2) ? W2 : W3;
        int n = idx >> 7, k = idx & 127;
        g_w[gidx] = __float2half_rn(W[k * D + n]);
    }
}

// ---------------------------------------------------------------------------
// 2: fill CSR adjacency — atomic-free: pos = off[dst] + seq
// ---------------------------------------------------------------------------
__global__ void k_fill(const int* __restrict__ src, const int* __restrict__ dst) {
    int gid = blockIdx.x * blockDim.x + threadIdx.x;
    if (gid < NEDGES / 2) {
        int2 s2 = ((const int2*)src)[gid];
        int2 d2 = ((const int2*)dst)[gid];
        int2 q2 = ((const int2*)g_seq)[gid];
        int p0 = g_off[d2.x] + q2.x;
        int p1 = g_off[d2.y] + q2.y;
        g_adj[p0] = s2.x;
        g_adj[p1] = s2.y;
    }
}

// ---------------------------------------------------------------------------
// gather (fp16, half-warp per node): x[i] = h[i] + sum_{s in adj(i)} h[s]
// ---------------------------------------------------------------------------
__global__ __launch_bounds__(THREADS)
void k_gather_h(const __half* __restrict__ h, __half* __restrict__ x) {
    int gwarp = (blockIdx.x * blockDim.x + threadIdx.x) >> 5;
    int lane = threadIdx.x & 31;
    int node = gwarp * 2 + (lane >> 4);
    int l16  = lane & 15;
    if (node >= NNODES) return;
    const uint4* hp = (const uint4*)h;   // 16 uint4 per row

    uint4 self = hp[(size_t)node * 16 + l16];
    float acc[8];
    {
        float2 f;
        f = h2f(self.x); acc[0] = f.x; acc[1] = f.y;
        f = h2f(self.y); acc[2] = f.x; acc[3] = f.y;
        f = h2f(self.z); acc[4] = f.x; acc[5] = f.y;
        f = h2f(self.w); acc[6] = f.x; acc[7] = f.y;
    }

    int beg = g_off[node], end = g_off[node + 1];
    int p = beg;
    for (; p + 4 <= end; p += 4) {
        int s0 = g_adj[p], s1 = g_adj[p + 1], s2 = g_adj[p + 2], s3 = g_adj[p + 3];
        uint4 v0 = hp[(size_t)s0 * 16 + l16];
        uint4 v1 = hp[(size_t)s1 * 16 + l16];
        uint4 v2 = hp[(size_t)s2 * 16 + l16];
        uint4 v3 = hp[(size_t)s3 * 16 + l16];
        float2 f;
        f = h2f(v0.x); acc[0] += f.x; acc[1] += f.y;
        f = h2f(v0.y); acc[2] += f.x; acc[3] += f.y;
        f = h2f(v0.z); acc[4] += f.x; acc[5] += f.y;
        f = h2f(v0.w); acc[6] += f.x; acc[7] += f.y;
        f = h2f(v1.x); acc[0] += f.x; acc[1] += f.y;
        f = h2f(v1.y); acc[2] += f.x; acc[3] += f.y;
        f = h2f(v1.z); acc[4] += f.x; acc[5] += f.y;
        f = h2f(v1.w); acc[6] += f.x; acc[7] += f.y;
        f = h2f(v2.x); acc[0] += f.x; acc[1] += f.y;
        f = h2f(v2.y); acc[2] += f.x; acc[3] += f.y;
        f = h2f(v2.z); acc[4] += f.x; acc[5] += f.y;
        f = h2f(v2.w); acc[6] += f.x; acc[7] += f.y;
        f = h2f(v3.x); acc[0] += f.x; acc[1] += f.y;
        f = h2f(v3.y); acc[2] += f.x; acc[3] += f.y;
        f = h2f(v3.z); acc[4] += f.x; acc[5] += f.y;
        f = h2f(v3.w); acc[6] += f.x; acc[7] += f.y;
    }
    for (; p < end; ++p) {
        int s = g_adj[p];
        uint4 v = hp[(size_t)s * 16 + l16];
        float2 f;
        f = h2f(v.x); acc[0] += f.x; acc[1] += f.y;
        f = h2f(v.y); acc[2] += f.x; acc[3] += f.y;
        f = h2f(v.z); acc[4] += f.x; acc[5] += f.y;
        f = h2f(v.w); acc[6] += f.x; acc[7] += f.y;
    }
    uint4 o;
    o.x = pack2h(acc[0], acc[1]);
    o.y = pack2h(acc[2], acc[3]);
    o.z = pack2h(acc[4], acc[5]);
    o.w = pack2h(acc[6], acc[7]);
    ((uint4*)x)[(size_t)node * 16 + l16] = o;
}

// ---------------------------------------------------------------------------
// HMMA fused MLP (pure fp16, staged weights): 3 CTAs/SM.
// ---------------------------------------------------------------------------
#define PB 272
#define SMEM_BA   0
#define SMEM_BB   512
#define SMEM_A    1024
#define ABUF_SZ   (128 * PB)                  // 34816
#define SMEM_W    (SMEM_A + ABUF_SZ)          // ONE weight matrix at a time
#define SMEM_TOTAL (SMEM_W + ABUF_SZ)         // 70656 B -> 3 CTAs/SM

template <int OUT_HALF>
__global__ __launch_bounds__(THREADS, 3)
void k_mlp_hmma(const __half* __restrict__ x,
                const __half* __restrict__ wa, const __half* __restrict__ wb,
                const float* __restrict__ ba, const float* __restrict__ bb,
                void* __restrict__ outp, int relu_out) {
    extern __shared__ char smem[];
    const uint32_t sb = smem_u32(smem);
    const int tid = threadIdx.x, wid = tid >> 5, lane = tid & 31;
    const int row0 = blockIdx.x * 128;

    if (tid < 128) {
        ((float*)(smem + SMEM_BA))[tid] = ba[tid];
        ((float*)(smem + SMEM_BB))[tid] = bb[tid];
    }

    #pragma unroll 1
    for (int i = tid; i < 128 * 16; i += THREADS) {
        int row = i >> 4, ch = i & 15;
        uint4 v = ((const uint4*)wa)[(row << 4) + ch];
        *(uint4*)(smem + SMEM_W + row * PB + ch * 16) = v;
    }

    {
        int r  = tid >> 1;
        int c0 = (tid & 1) * 128;
        int grow = row0 + r;
        char* ap = smem + SMEM_A + r * PB + c0;
        if (grow < NNODES) {
            const char* xp = (const char*)(x + (size_t)grow * D) + c0;
            #pragma unroll
            for (int c = 0; c < 128; c += 16)
                *(uint4*)(ap + c) = *(const uint4*)(xp + c);
        } else {
            #pragma unroll
            for (int c = 0; c < 128; c += 16)
                *(uint4*)(ap + c) = make_uint4(0u, 0u, 0u, 0u);
        }
    }
    __syncthreads();

    const int warp_m = wid & 3;
    const int warp_n = wid >> 2;
    const int m0 = warp_m * 32;
    const int n0 = warp_n * 64;

    const uint32_t a_off = (uint32_t)((m0 + (lane & 15)) * PB + (lane >> 4) * 16);
    const uint32_t b_off = (uint32_t)((n0 + ((lane >> 4) << 3) + (lane & 7)) * PB
                                      + ((lane >> 3) & 1) * 16);

    const uint32_t Abuf = sb + SMEM_A;
    const uint32_t Wbuf = sb + SMEM_W;

    float acc[2][8][4];

    auto run_gemm = [&]() {
        #pragma unroll
        for (int tm = 0; tm < 2; tm++)
            #pragma unroll
            for (int tn = 0; tn < 8; tn++)
                #pragma unroll
                for (int q = 0; q < 4; q++) acc[tm][tn][q] = 0.f;

        #pragma unroll
        for (int s = 0; s < 8; s++) {
            const uint32_t kb = s * 32;
            uint32_t ah[2][4];
            ldsm_x4(ah[0][0], ah[0][1], ah[0][2], ah[0][3], Abuf + a_off + kb);
            ldsm_x4(ah[1][0], ah[1][1], ah[1][2], ah[1][3], Abuf + a_off + 16 * PB + kb);

            #pragma unroll
            for (int p = 0; p < 4; p++) {
                uint32_t b0, b1, b2, b3;
                ldsm_x4(b0, b1, b2, b3, Wbuf + b_off + p * 16 * PB + kb);
                #pragma unroll
                for (int tm = 0; tm < 2; tm++) {
                    float* c0 = acc[tm][p * 2];
                    float* c1 = acc[tm][p * 2 + 1];
                    mma_f16(c0[0], c0[1], c0[2], c0[3],
                            ah[tm][0], ah[tm][1], ah[tm][2], ah[tm][3], b0, b1);
                    mma_f16(c1[0], c1[1], c1[2], c1[3],
                            ah[tm][0], ah[tm][1], ah[tm][2], ah[tm][3], b2, b3);
                }
            }
        }
    };

    // ---- GEMM1: A @ Wa ----
    run_gemm();
    __syncthreads();

    // ---- load Wb over Wa + epilogue 1 ----
    #pragma unroll 1
    for (int i = tid; i < 128 * 16; i += THREADS) {
        int row = i >> 4, ch = i & 15;
        uint4 v = ((const uint4*)wb)[(row << 4) + ch];
        *(uint4*)(smem + SMEM_W + row * PB + ch * 16) = v;
    }
    {
        const float* bav = (const float*)(smem + SMEM_BA);
        #pragma unroll
        for (int tm = 0; tm < 2; tm++) {
            #pragma unroll
            for (int tn = 0; tn < 8; tn++) {
                const int col = n0 + tn * 8 + (lane & 3) * 2;
                const float b0v = bav[col], b1v = bav[col + 1];
                const int r_lo = m0 + tm * 16 + (lane >> 2);
                float v0 = fmaxf(acc[tm][tn][0] + b0v, 0.f);
                float v1 = fmaxf(acc[tm][tn][1] + b1v, 0.f);
                float v2 = fmaxf(acc[tm][tn][2] + b0v, 0.f);
                float v3 = fmaxf(acc[tm][tn][3] + b1v, 0.f);
                *(uint32_t*)(smem + SMEM_A + r_lo * PB + col * 2)       = pack2h(v0, v1);
                *(uint32_t*)(smem + SMEM_A + (r_lo + 8) * PB + col * 2) = pack2h(v2, v3);
            }
        }
    }
    __syncthreads();

    // ---- GEMM2: H @ Wb ----
    run_gemm();

    // ---- epilogue 2 ----
    {
        const float* bbv = (const float*)(smem + SMEM_BB);
        #pragma unroll
        for (int tm = 0; tm < 2; tm++) {
            #pragma unroll
            for (int tn = 0; tn < 8; tn++) {
                const int col = n0 + tn * 8 + (lane & 3) * 2;
                const float b0v = bbv[col], b1v = bbv[col + 1];
                const int r_lo = row0 + m0 + tm * 16 + (lane >> 2);
                float v0 = acc[tm][tn][0] + b0v;
                float v1 = acc[tm][tn][1] + b1v;
                float v2 = acc[tm][tn][2] + b0v;
                float v3 = acc[tm][tn][3] + b1v;
                if (relu_out) {
                    v0 = fmaxf(v0, 0.f); v1 = fmaxf(v1, 0.f);
                    v2 = fmaxf(v2, 0.f); v3 = fmaxf(v3, 0.f);
                }
                if (OUT_HALF) {
                    __half* out = (__half*)outp;
                    if (r_lo < NNODES)
                        *(uint32_t*)(out + (size_t)r_lo * D + col) = pack2h(v0, v1);
                    if (r_lo + 8 < NNODES)
                        *(uint32_t*)(out + (size_t)(r_lo + 8) * D + col) = pack2h(v2, v3);
                } else {
                    float* out = (float*)outp;
                    if (r_lo < NNODES)
                        *(float2*)(out + (size_t)r_lo * D + col) = make_float2(v0, v1);
                    if (r_lo + 8 < NNODES)
                        *(float2*)(out + (size_t)(r_lo + 8) * D + col) = make_float2(v2, v3);
                }
            }
        }
    }
}

// ---------------------------------------------------------------------------
// launch
// ---------------------------------------------------------------------------
extern "C" void kernel_launch(void* const* d_in, const int* in_sizes, int n_in,
                              void* d_out, int out_size) {
    const float* inputs = (const float*)d_in[0];
    const int*   src    = (const int*)  d_in[1];
    const int*   dst    = (const int*)  d_in[2];
    const float* W1a    = (const float*)d_in[3];
    const float* b1a    = (const float*)d_in[4];
    const float* W1b    = (const float*)d_in[5];
    const float* b1b    = (const float*)d_in[6];
    const float* W2a    = (const float*)d_in[7];
    const float* b2a    = (const float*)d_in[8];
    const float* W2b    = (const float*)d_in[9];
    const float* b2b    = (const float*)d_in[10];

    __half *ginh = nullptr, *gxh = nullptr, *ghh = nullptr, *gw = nullptr;
    cudaGetSymbolAddress((void**)&ginh, g_inh);
    cudaGetSymbolAddress((void**)&gxh, g_xh);
    cudaGetSymbolAddress((void**)&ghh, g_hh);
    cudaGetSymbolAddress((void**)&gw, g_w);

    cudaFuncSetAttribute(k_mlp_hmma<1>, cudaFuncAttributeMaxDynamicSharedMemorySize, SMEM_TOTAL);
    cudaFuncSetAttribute(k_mlp_hmma<0>, cudaFuncAttributeMaxDynamicSharedMemorySize, SMEM_TOTAL);

    const int edge2_blocks = (NEDGES / 2 + THREADS - 1) / THREADS;   // 1172
    const int gath_blocks  = (((NNODES + 1) / 2) * 32 + THREADS - 1) / THREADS; // 3125
    const int mlp_blocks   = (NNODES + 127) / 128;

    k_hist_cvt<<<edge2_blocks, THREADS>>>(dst, inputs);           // 0
    k_scan_wsplit<<<256, 256>>>(W1a, W1b, W2a, W2b);              // 1
    k_fill<<<edge2_blocks, THREADS>>>(src, dst);                  // 2

    // layer 1
    k_gather_h<<<gath_blocks, THREADS>>>(ginh, gxh);              // 3  <- profiled
    k_mlp_hmma<1><<<mlp_blocks, THREADS, SMEM_TOTAL>>>(           // 4
        gxh, gw + 0 * D * D, gw + 1 * D * D, b1a, b1b, ghh, 1);

    // layer 2
    k_gather_h<<<gath_blocks, THREADS>>>(ghh, gxh);               // 5
    k_mlp_hmma<0><<<mlp_blocks, THREADS, SMEM_TOTAL>>>(           // 6
        gxh, gw + 2 * D * D, gw + 3 * D * D, b2a, b2b, d_out, 0);
}

// round 15
// speedup vs baseline: 1.0413x; 1.0413x over previous
#include <cuda_runtime.h>
#include <cuda_fp16.h>
#include <cstdint>

#define D 128
#define NNODES 50000
#define NEDGES 600000
#define THREADS 256
#define SCAN_BLOCKS ((NNODES + 255) / 256)   // 196

// ---------------------------------------------------------------------------
// Device-global scratch (allocation-free rule)
// ---------------------------------------------------------------------------
__device__ __half g_inh[(size_t)NNODES * D];  // fp16 copy of inputs
__device__ __half g_xh[(size_t)NNODES * D];   // gathered features (fp16)
__device__ __half g_hh[(size_t)NNODES * D];   // layer-1 output (fp16)
__device__ int   g_deg[NNODES];
__device__ int   g_off[NNODES + 1];
__device__ int   g_seq[NEDGES];               // per-edge within-node sequence #
__device__ int   g_adj[NEDGES];
__device__ int   g_bsum[256];                 // block aggregates -> excl prefixes
__device__ int   g_done;                      // arrival counter (reset each call)
__device__ volatile int g_ready;              // prefix-ready flag (reset each call)
// fp16 weights, K-major [n][k], 4 matrices: W1a, W1b, W2a, W2b
__device__ __half g_w[4 * D * D];

// ---------------------------------------------------------------------------
// helpers
// ---------------------------------------------------------------------------
__device__ __forceinline__ uint32_t smem_u32(const void* p) {
    uint32_t a;
    asm("{ .reg .u64 t; cvta.to.shared.u64 t, %1; cvt.u32.u64 %0, t; }" : "=r"(a) : "l"(p));
    return a;
}

__device__ __forceinline__ void ldsm_x4(uint32_t& r0, uint32_t& r1, uint32_t& r2, uint32_t& r3,
                                        uint32_t addr) {
    asm volatile("ldmatrix.sync.aligned.m8n8.x4.shared.b16 {%0,%1,%2,%3}, [%4];"
                 : "=r"(r0), "=r"(r1), "=r"(r2), "=r"(r3) : "r"(addr));
}

__device__ __forceinline__ void mma_f16(float& c0, float& c1, float& c2, float& c3,
                                        uint32_t a0, uint32_t a1, uint32_t a2, uint32_t a3,
                                        uint32_t b0, uint32_t b1) {
    asm volatile("mma.sync.aligned.m16n8k16.row.col.f32.f16.f16.f32 "
                 "{%0,%1,%2,%3}, {%4,%5,%6,%7}, {%8,%9}, {%0,%1,%2,%3};"
                 : "+f"(c0), "+f"(c1), "+f"(c2), "+f"(c3)
                 : "r"(a0), "r"(a1), "r"(a2), "r"(a3), "r"(b0), "r"(b1));
}

__device__ __forceinline__ uint32_t pack2h(float v0, float v1) {
    __half2 h = __floats2half2_rn(v0, v1);
    return *(uint32_t*)&h;
}

__device__ __forceinline__ float2 h2f(uint32_t u) {
    __half2 h = *(__half2*)&u;
    return __half22float2(h);
}

__device__ __forceinline__ uint32_t hadd2u(uint32_t a, uint32_t b) {
    __half2 r = __hadd2(*(__half2*)&a, *(__half2*)&b);
    return *(uint32_t*)&r;
}

// ---------------------------------------------------------------------------
// 0: histogram (stores per-edge seq) + fp32->fp16 conversion + epoch reset
// ---------------------------------------------------------------------------
__global__ void k_hist_cvt(const int* __restrict__ dst, const float* __restrict__ inputs) {
    int gid = blockIdx.x * blockDim.x + threadIdx.x;
    if (gid == 0) { g_done = 0; g_ready = 0; }   // reset scan epoch for this call
    if (gid < NEDGES / 2) {
        int2 d2 = ((const int2*)dst)[gid];
        int s0 = atomicAdd(&g_deg[d2.x], 1);
        int s1 = atomicAdd(&g_deg[d2.y], 1);
        ((int2*)g_seq)[gid] = make_int2(s0, s1);
    }
    const int total = NNODES * D / 8;
    const int stride = gridDim.x * blockDim.x;
    for (int i = gid; i < total; i += stride) {
        float4 a = ((const float4*)inputs)[i * 2];
        float4 b = ((const float4*)inputs)[i * 2 + 1];
        uint4 o;
        o.x = pack2h(a.x, a.y);
        o.y = pack2h(a.z, a.w);
        o.z = pack2h(b.x, b.y);
        o.w = pack2h(b.z, b.w);
        ((uint4*)g_inh)[i] = o;
    }
}

// ---------------------------------------------------------------------------
// 1: SINGLE-PASS scan (last-block pattern) + fused weight convert
// ---------------------------------------------------------------------------
__global__ __launch_bounds__(256)
void k_scan_wsplit(const float* __restrict__ W0, const float* __restrict__ W1,
                   const float* __restrict__ W2, const float* __restrict__ W3) {
    __shared__ int wsum[8];
    __shared__ int sh_last;
    const int b = blockIdx.x, tid = threadIdx.x, lane = tid & 31, wd = tid >> 5;

    if (b < SCAN_BLOCKS) {
        int i = b * 256 + tid;
        int v = (i < NNODES) ? g_deg[i] : 0;
        if (i < NNODES) g_deg[i] = 0;            // re-zero for next call
        int s = v;
        #pragma unroll
        for (int o = 1; o < 32; o <<= 1) {
            int t = __shfl_up_sync(0xFFFFFFFFu, s, o);
            if (lane >= o) s += t;
        }
        if (lane == 31) wsum[wd] = s;
        __syncthreads();
        if (wd == 0) {
            int x = (lane < 8) ? wsum[lane] : 0;
            #pragma unroll
            for (int o = 1; o < 8; o <<= 1) {
                int t = __shfl_up_sync(0xFFFFFFFFu, x, o);
                if (lane >= o) x += t;
            }
            if (lane < 8) wsum[lane] = x;
        }
        __syncthreads();
        int excl_local = (wd ? wsum[wd - 1] : 0) + s - v;

        if (tid == 255) {
            g_bsum[b] = wsum[7];
            __threadfence();
            int d = atomicAdd(&g_done, 1);
            sh_last = (d == SCAN_BLOCKS - 1) ? 1 : 0;
        }
        __syncthreads();

        if (sh_last) {
            __threadfence();
            int v2 = (tid < SCAN_BLOCKS) ? g_bsum[tid] : 0;
            int s2 = v2;
            #pragma unroll
            for (int o = 1; o < 32; o <<= 1) {
                int t = __shfl_up_sync(0xFFFFFFFFu, s2, o);
                if (lane >= o) s2 += t;
            }
            if (lane == 31) wsum[wd] = s2;
            __syncthreads();
            if (wd == 0) {
                int x = (lane < 8) ? wsum[lane] : 0;
                #pragma unroll
                for (int o = 1; o < 8; o <<= 1) {
                    int t = __shfl_up_sync(0xFFFFFFFFu, x, o);
                    if (lane >= o) x += t;
                }
                if (lane < 8) wsum[lane] = x;
            }
            __syncthreads();
            int excl2 = (wd ? wsum[wd - 1] : 0) + s2 - v2;
            if (tid < SCAN_BLOCKS) g_bsum[tid] = excl2;
            __threadfence();
            __syncthreads();
            if (tid == 0) g_ready = 1;
        }

        if (tid == 0) {
            while (g_ready == 0) { __nanosleep(40); }
        }
        __syncthreads();
        __threadfence();

        int pre = g_bsum[b];
        if (i < NNODES) g_off[i] = excl_local + pre;
        if (b == 0 && tid == 0) g_off[NNODES] = NEDGES;
    }

    // fused weight transpose + fp16 convert
    {
        int gidx = b * 256 + tid;
        int mat = gidx >> 14;
        int idx = gidx & 16383;
        const float* W = (mat == 0) ? W0 : (mat == 1) ? W1 : (mat == 2) ? W2 : W3;
        int n = idx >> 7, k = idx & 127;
        g_w[gidx] = __float2half_rn(W[k * D + n]);
    }
}

// ---------------------------------------------------------------------------
// 2: fill CSR adjacency — atomic-free: pos = off[dst] + seq
// ---------------------------------------------------------------------------
__global__ void k_fill(const int* __restrict__ src, const int* __restrict__ dst) {
    int gid = blockIdx.x * blockDim.x + threadIdx.x;
    if (gid < NEDGES / 2) {
        int2 s2 = ((const int2*)src)[gid];
        int2 d2 = ((const int2*)dst)[gid];
        int2 q2 = ((const int2*)g_seq)[gid];
        int p0 = g_off[d2.x] + q2.x;
        int p1 = g_off[d2.y] + q2.y;
        g_adj[p0] = s2.x;
        g_adj[p1] = s2.y;
    }
}

// ---------------------------------------------------------------------------
// gather (fp16, half-warp per node): x[i] = h[i] + sum_{s in adj(i)} h[s]
// fp16 pairwise pre-reduce (HADD2) -> fp32 accumulate; 32-bit addressing.
// ---------------------------------------------------------------------------
__global__ __launch_bounds__(THREADS)
void k_gather_h(const __half* __restrict__ h, __half* __restrict__ x) {
    int gwarp = (blockIdx.x * blockDim.x + threadIdx.x) >> 5;
    int lane = threadIdx.x & 31;
    int node = gwarp * 2 + (lane >> 4);
    int l16  = lane & 15;
    if (node >= NNODES) return;
    const char* hb = (const char*)h;
    const uint32_t lo16 = (uint32_t)(l16 << 4);   // lane byte offset within row

    uint4 self = *(const uint4*)(hb + (((uint32_t)node << 8) | lo16));
    float acc[8];
    {
        float2 f;
        f = h2f(self.x); acc[0] = f.x; acc[1] = f.y;
        f = h2f(self.y); acc[2] = f.x; acc[3] = f.y;
        f = h2f(self.z); acc[4] = f.x; acc[5] = f.y;
        f = h2f(self.w); acc[6] = f.x; acc[7] = f.y;
    }

    int beg = g_off[node], end = g_off[node + 1];
    int p = beg;
    for (; p + 4 <= end; p += 4) {
        uint32_t o0 = ((uint32_t)g_adj[p]     << 8) | lo16;
        uint32_t o1 = ((uint32_t)g_adj[p + 1] << 8) | lo16;
        uint32_t o2 = ((uint32_t)g_adj[p + 2] << 8) | lo16;
        uint32_t o3 = ((uint32_t)g_adj[p + 3] << 8) | lo16;
        uint4 v0 = *(const uint4*)(hb + o0);
        uint4 v1 = *(const uint4*)(hb + o1);
        uint4 v2 = *(const uint4*)(hb + o2);
        uint4 v3 = *(const uint4*)(hb + o3);
        // fp16 pairwise pre-reduce (one rounding per pair), then fp32 accumulate
        uint32_t p01x = hadd2u(v0.x, v1.x), p23x = hadd2u(v2.x, v3.x);
        uint32_t p01y = hadd2u(v0.y, v1.y), p23y = hadd2u(v2.y, v3.y);
        uint32_t p01z = hadd2u(v0.z, v1.z), p23z = hadd2u(v2.z, v3.z);
        uint32_t p01w = hadd2u(v0.w, v1.w), p23w = hadd2u(v2.w, v3.w);
        float2 f;
        f = h2f(p01x); acc[0] += f.x; acc[1] += f.y;
        f = h2f(p23x); acc[0] += f.x; acc[1] += f.y;
        f = h2f(p01y); acc[2] += f.x; acc[3] += f.y;
        f = h2f(p23y); acc[2] += f.x; acc[3] += f.y;
        f = h2f(p01z); acc[4] += f.x; acc[5] += f.y;
        f = h2f(p23z); acc[4] += f.x; acc[5] += f.y;
        f = h2f(p01w); acc[6] += f.x; acc[7] += f.y;
        f = h2f(p23w); acc[6] += f.x; acc[7] += f.y;
    }
    for (; p < end; ++p) {
        uint32_t o = ((uint32_t)g_adj[p] << 8) | lo16;
        uint4 v = *(const uint4*)(hb + o);
        float2 f;
        f = h2f(v.x); acc[0] += f.x; acc[1] += f.y;
        f = h2f(v.y); acc[2] += f.x; acc[3] += f.y;
        f = h2f(v.z); acc[4] += f.x; acc[5] += f.y;
        f = h2f(v.w); acc[6] += f.x; acc[7] += f.y;
    }
    uint4 o;
    o.x = pack2h(acc[0], acc[1]);
    o.y = pack2h(acc[2], acc[3]);
    o.z = pack2h(acc[4], acc[5]);
    o.w = pack2h(acc[6], acc[7]);
    *(uint4*)((char*)x + (((uint32_t)node << 8) | lo16)) = o;
}

// ---------------------------------------------------------------------------
// HMMA fused MLP (pure fp16, staged weights): 3 CTAs/SM.
// ---------------------------------------------------------------------------
#define PB 272
#define SMEM_BA   0
#define SMEM_BB   512
#define SMEM_A    1024
#define ABUF_SZ   (128 * PB)                  // 34816
#define SMEM_W    (SMEM_A + ABUF_SZ)          // ONE weight matrix at a time
#define SMEM_TOTAL (SMEM_W + ABUF_SZ)         // 70656 B -> 3 CTAs/SM

template <int OUT_HALF>
__global__ __launch_bounds__(THREADS, 3)
void k_mlp_hmma(const __half* __restrict__ x,
                const __half* __restrict__ wa, const __half* __restrict__ wb,
                const float* __restrict__ ba, const float* __restrict__ bb,
                void* __restrict__ outp, int relu_out) {
    extern __shared__ char smem[];
    const uint32_t sb = smem_u32(smem);
    const int tid = threadIdx.x, wid = tid >> 5, lane = tid & 31;
    const int row0 = blockIdx.x * 128;

    if (tid < 128) {
        ((float*)(smem + SMEM_BA))[tid] = ba[tid];
        ((float*)(smem + SMEM_BB))[tid] = bb[tid];
    }

    #pragma unroll 1
    for (int i = tid; i < 128 * 16; i += THREADS) {
        int row = i >> 4, ch = i & 15;
        uint4 v = ((const uint4*)wa)[(row << 4) + ch];
        *(uint4*)(smem + SMEM_W + row * PB + ch * 16) = v;
    }

    {
        int r  = tid >> 1;
        int c0 = (tid & 1) * 128;
        int grow = row0 + r;
        char* ap = smem + SMEM_A + r * PB + c0;
        if (grow < NNODES) {
            const char* xp = (const char*)(x + (size_t)grow * D) + c0;
            #pragma unroll
            for (int c = 0; c < 128; c += 16)
                *(uint4*)(ap + c) = *(const uint4*)(xp + c);
        } else {
            #pragma unroll
            for (int c = 0; c < 128; c += 16)
                *(uint4*)(ap + c) = make_uint4(0u, 0u, 0u, 0u);
        }
    }
    __syncthreads();

    const int warp_m = wid & 3;
    const int warp_n = wid >> 2;
    const int m0 = warp_m * 32;
    const int n0 = warp_n * 64;

    const uint32_t a_off = (uint32_t)((m0 + (lane & 15)) * PB + (lane >> 4) * 16);
    const uint32_t b_off = (uint32_t)((n0 + ((lane >> 4) << 3) + (lane & 7)) * PB
                                      + ((lane >> 3) & 1) * 16);

    const uint32_t Abuf = sb + SMEM_A;
    const uint32_t Wbuf = sb + SMEM_W;

    float acc[2][8][4];

    auto run_gemm = [&]() {
        #pragma unroll
        for (int tm = 0; tm < 2; tm++)
            #pragma unroll
            for (int tn = 0; tn < 8; tn++)
                #pragma unroll
                for (int q = 0; q < 4; q++) acc[tm][tn][q] = 0.f;

        #pragma unroll
        for (int s = 0; s < 8; s++) {
            const uint32_t kb = s * 32;
            uint32_t ah[2][4];
            ldsm_x4(ah[0][0], ah[0][1], ah[0][2], ah[0][3], Abuf + a_off + kb);
            ldsm_x4(ah[1][0], ah[1][1], ah[1][2], ah[1][3], Abuf + a_off + 16 * PB + kb);

            #pragma unroll
            for (int p = 0; p < 4; p++) {
                uint32_t b0, b1, b2, b3;
                ldsm_x4(b0, b1, b2, b3, Wbuf + b_off + p * 16 * PB + kb);
                #pragma unroll
                for (int tm = 0; tm < 2; tm++) {
                    float* c0 = acc[tm][p * 2];
                    float* c1 = acc[tm][p * 2 + 1];
                    mma_f16(c0[0], c0[1], c0[2], c0[3],
                            ah[tm][0], ah[tm][1], ah[tm][2], ah[tm][3], b0, b1);
                    mma_f16(c1[0], c1[1], c1[2], c1[3],
                            ah[tm][0], ah[tm][1], ah[tm][2], ah[tm][3], b2, b3);
                }
            }
        }
    };

    // ---- GEMM1: A @ Wa ----
    run_gemm();
    __syncthreads();

    // ---- load Wb over Wa + epilogue 1 ----
    #pragma unroll 1
    for (int i = tid; i < 128 * 16; i += THREADS) {
        int row = i >> 4, ch = i & 15;
        uint4 v = ((const uint4*)wb)[(row << 4) + ch];
        *(uint4*)(smem + SMEM_W + row * PB + ch * 16) = v;
    }
    {
        const float* bav = (const float*)(smem + SMEM_BA);
        #pragma unroll
        for (int tm = 0; tm < 2; tm++) {
            #pragma unroll
            for (int tn = 0; tn < 8; tn++) {
                const int col = n0 + tn * 8 + (lane & 3) * 2;
                const float b0v = bav[col], b1v = bav[col + 1];
                const int r_lo = m0 + tm * 16 + (lane >> 2);
                float v0 = fmaxf(acc[tm][tn][0] + b0v, 0.f);
                float v1 = fmaxf(acc[tm][tn][1] + b1v, 0.f);
                float v2 = fmaxf(acc[tm][tn][2] + b0v, 0.f);
                float v3 = fmaxf(acc[tm][tn][3] + b1v, 0.f);
                *(uint32_t*)(smem + SMEM_A + r_lo * PB + col * 2)       = pack2h(v0, v1);
                *(uint32_t*)(smem + SMEM_A + (r_lo + 8) * PB + col * 2) = pack2h(v2, v3);
            }
        }
    }
    __syncthreads();

    // ---- GEMM2: H @ Wb ----
    run_gemm();

    // ---- epilogue 2 ----
    {
        const float* bbv = (const float*)(smem + SMEM_BB);
        #pragma unroll
        for (int tm = 0; tm < 2; tm++) {
            #pragma unroll
            for (int tn = 0; tn < 8; tn++) {
                const int col = n0 + tn * 8 + (lane & 3) * 2;
                const float b0v = bbv[col], b1v = bbv[col + 1];
                const int r_lo = row0 + m0 + tm * 16 + (lane >> 2);
                float v0 = acc[tm][tn][0] + b0v;
                float v1 = acc[tm][tn][1] + b1v;
                float v2 = acc[tm][tn][2] + b0v;
                float v3 = acc[tm][tn][3] + b1v;
                if (relu_out) {
                    v0 = fmaxf(v0, 0.f); v1 = fmaxf(v1, 0.f);
                    v2 = fmaxf(v2, 0.f); v3 = fmaxf(v3, 0.f);
                }
                if (OUT_HALF) {
                    __half* out = (__half*)outp;
                    if (r_lo < NNODES)
                        *(uint32_t*)(out + (size_t)r_lo * D + col) = pack2h(v0, v1);
                    if (r_lo + 8 < NNODES)
                        *(uint32_t*)(out + (size_t)(r_lo + 8) * D + col) = pack2h(v2, v3);
                } else {
                    float* out = (float*)outp;
                    if (r_lo < NNODES)
                        *(float2*)(out + (size_t)r_lo * D + col) = make_float2(v0, v1);
                    if (r_lo + 8 < NNODES)
                        *(float2*)(out + (size_t)(r_lo + 8) * D + col) = make_float2(v2, v3);
                }
            }
        }
    }
}

// ---------------------------------------------------------------------------
// launch
// ---------------------------------------------------------------------------
extern "C" void kernel_launch(void* const* d_in, const int* in_sizes, int n_in,
                              void* d_out, int out_size) {
    const float* inputs = (const float*)d_in[0];
    const int*   src    = (const int*)  d_in[1];
    const int*   dst    = (const int*)  d_in[2];
    const float* W1a    = (const float*)d_in[3];
    const float* b1a    = (const float*)d_in[4];
    const float* W1b    = (const float*)d_in[5];
    const float* b1b    = (const float*)d_in[6];
    const float* W2a    = (const float*)d_in[7];
    const float* b2a    = (const float*)d_in[8];
    const float* W2b    = (const float*)d_in[9];
    const float* b2b    = (const float*)d_in[10];

    __half *ginh = nullptr, *gxh = nullptr, *ghh = nullptr, *gw = nullptr;
    cudaGetSymbolAddress((void**)&ginh, g_inh);
    cudaGetSymbolAddress((void**)&gxh, g_xh);
    cudaGetSymbolAddress((void**)&ghh, g_hh);
    cudaGetSymbolAddress((void**)&gw, g_w);

    cudaFuncSetAttribute(k_mlp_hmma<1>, cudaFuncAttributeMaxDynamicSharedMemorySize, SMEM_TOTAL);
    cudaFuncSetAttribute(k_mlp_hmma<0>, cudaFuncAttributeMaxDynamicSharedMemorySize, SMEM_TOTAL);

    const int edge2_blocks = (NEDGES / 2 + THREADS - 1) / THREADS;   // 1172
    const int gath_blocks  = (((NNODES + 1) / 2) * 32 + THREADS - 1) / THREADS; // 3125
    const int mlp_blocks   = (NNODES + 127) / 128;

    k_hist_cvt<<<edge2_blocks, THREADS>>>(dst, inputs);           // 0
    k_scan_wsplit<<<256, 256>>>(W1a, W1b, W2a, W2b);              // 1
    k_fill<<<edge2_blocks, THREADS>>>(src, dst);                  // 2

    // layer 1
    k_gather_h<<<gath_blocks, THREADS>>>(ginh, gxh);              // 3  <- profiled
    k_mlp_hmma<1><<<mlp_blocks, THREADS, SMEM_TOTAL>>>(           // 4
        gxh, gw + 0 * D * D, gw + 1 * D * D, b1a, b1b, ghh, 1);

    // layer 2
    k_gather_h<<<gath_blocks, THREADS>>>(ghh, gxh);               // 5
    k_mlp_hmma<0><<<mlp_blocks, THREADS, SMEM_TOTAL>>>(           // 6
        gxh, gw + 2 * D * D, gw + 3 * D * D, b2a, b2b, d_out, 0);
}